// round 1
// baseline (speedup 1.0000x reference)
#include <cuda_runtime.h>

// Problem constants (fixed by the dataset)
#define HH   1024
#define WW   2048
#define GW   (WW + 2)        // padded grid width  = 2050
#define GH   (HH + 2)        // padded grid height = 1026
#define GSZ  (GH * GW)       // 2,103,300 floats (divisible by 4)
#define COUT 64
#define NMAX 1000000
#define BN_EPS 1e-5f
#define STATS_BLOCKS 592

// Scratch (static __device__ arrays — no allocation)
__device__ float  g_grid[GSZ];                     // ~8.4 MB padded dense grid
__device__ float4 g_nb0[NMAX];                     // s[0..3] packed
__device__ float4 g_nb1[NMAX];                     // s[4..7] packed
__device__ float  g_nb8[NMAX];                     // s[8]
__device__ float  g_part[STATS_BLOCKS * 54];       // per-block stat partials
__device__ float  g_wf[9 * COUT];                  // BN-folded weights
__device__ float  g_bf[COUT];                      // BN-folded bias

// ---------------------------------------------------------------------------
// K0: zero the padded grid (float4 stream)
// ---------------------------------------------------------------------------
__global__ void k_zero_grid() {
    const int n4 = GSZ / 4;
    float4 z = make_float4(0.f, 0.f, 0.f, 0.f);
    for (int j = blockIdx.x * blockDim.x + threadIdx.x; j < n4;
         j += gridDim.x * blockDim.x)
        reinterpret_cast<float4*>(g_grid)[j] = z;
}

// ---------------------------------------------------------------------------
// K1: scatter active features into the padded grid
// ---------------------------------------------------------------------------
__global__ void k_scatter(const int2* __restrict__ coords,
                          const float* __restrict__ feats, int n) {
    int i = blockIdx.x * blockDim.x + threadIdx.x;
    if (i < n) {
        int2 c = coords[i];                        // c.x = y, c.y = x
        g_grid[(c.x + 1) * GW + (c.y + 1)] = feats[i];
    }
}

// ---------------------------------------------------------------------------
// K2: per-point gather of the 9 neighbors; pack into coalesced nb arrays;
//     accumulate sum9[9] + upper-tri second-moment M[45] into per-block
//     partials (deterministic — no float atomics).
// ---------------------------------------------------------------------------
__global__ __launch_bounds__(256) void k_gather_stats(
        const int2* __restrict__ coords, int n) {
    float acc[54];
#pragma unroll
    for (int i = 0; i < 54; i++) acc[i] = 0.f;

    const int tid    = blockIdx.x * blockDim.x + threadIdx.x;
    const int stride = gridDim.x * blockDim.x;

    for (int p = tid; p < n; p += stride) {
        int2 c = coords[p];
        const float* base = g_grid + c.x * GW + c.y;   // (y-1+1, x-1+1)
        float s[9];
#pragma unroll
        for (int r = 0; r < 3; r++)
#pragma unroll
            for (int q = 0; q < 3; q++)
                s[r * 3 + q] = __ldg(base + r * GW + q);

        g_nb0[p] = make_float4(s[0], s[1], s[2], s[3]);
        g_nb1[p] = make_float4(s[4], s[5], s[6], s[7]);
        g_nb8[p] = s[8];

#pragma unroll
        for (int k = 0; k < 9; k++) acc[k] += s[k];
        int idx = 9;
#pragma unroll
        for (int j = 0; j < 9; j++)
#pragma unroll
            for (int k = j; k < 9; k++) acc[idx++] += s[j] * s[k];
    }

    // block reduction: warp shfl -> shared -> per-block partial
    __shared__ float red[54 * 8];
    const int w = threadIdx.x >> 5, lane = threadIdx.x & 31;
#pragma unroll
    for (int i = 0; i < 54; i++) {
        float v = acc[i];
#pragma unroll
        for (int o = 16; o; o >>= 1) v += __shfl_xor_sync(0xffffffffu, v, o);
        if (lane == 0) red[i * 8 + w] = v;
    }
    __syncthreads();
    if (threadIdx.x < 54) {
        float v = 0.f;
#pragma unroll
        for (int ww = 0; ww < 8; ww++) v += red[threadIdx.x * 8 + ww];
        g_part[blockIdx.x * 54 + threadIdx.x] = v;
    }
}

// ---------------------------------------------------------------------------
// K3: reduce partials, compute per-channel BN stats analytically, fold BN
//     into the conv weights:  W'[k,c] = W[k,c]*scale_c ; b'[c] = beta - mean*scale
// ---------------------------------------------------------------------------
__global__ void k_finalize(const float* __restrict__ weight,   // [9,1,64]
                           const float* __restrict__ gamma,
                           const float* __restrict__ beta, int n) {
    __shared__ float st[54];
    const int t = threadIdx.x;
    if (t < 54) {
        float v0 = 0.f, v1 = 0.f, v2 = 0.f, v3 = 0.f;
        int b = 0;
        for (; b + 3 < STATS_BLOCKS; b += 4) {
            v0 += g_part[(b + 0) * 54 + t];
            v1 += g_part[(b + 1) * 54 + t];
            v2 += g_part[(b + 2) * 54 + t];
            v3 += g_part[(b + 3) * 54 + t];
        }
        for (; b < STATS_BLOCKS; b++) v0 += g_part[b * 54 + t];
        st[t] = (v0 + v1) + (v2 + v3);
    }
    __syncthreads();
    if (t < COUT) {
        float w[9];
#pragma unroll
        for (int k = 0; k < 9; k++) w[k] = weight[k * COUT + t];
        const float invn = 1.f / (float)n;

        float mean = 0.f;
#pragma unroll
        for (int k = 0; k < 9; k++) mean += st[k] * w[k];
        mean *= invn;

        float q = 0.f;
        int idx = 9;
#pragma unroll
        for (int j = 0; j < 9; j++)
#pragma unroll
            for (int k = j; k < 9; k++) {
                float term = st[idx++] * w[j] * w[k];
                q += (j == k) ? term : 2.f * term;
            }
        float var   = fmaxf(q * invn - mean * mean, 0.f);
        float scale = gamma[t] * rsqrtf(var + BN_EPS);
#pragma unroll
        for (int k = 0; k < 9; k++) g_wf[k * COUT + t] = w[k] * scale;
        g_bf[t] = beta[t] - mean * scale;
    }
}

// ---------------------------------------------------------------------------
// K4: output pass. One warp per point; lane l computes channels 2l, 2l+1 and
//     writes a float2 -> each warp writes one fully-coalesced 256 B output row.
//     Neighbor values arrive via 2x LDG.128 + 1x LDG.32 uniform broadcasts.
// ---------------------------------------------------------------------------
__global__ __launch_bounds__(256) void k_output(float2* __restrict__ out, int n) {
    const int lane = threadIdx.x & 31;
    const int gw   = (blockIdx.x * blockDim.x + threadIdx.x) >> 5;
    const int nw   = (gridDim.x * blockDim.x) >> 5;
    const int c0   = lane * 2;

    float wa[9], wb[9];
#pragma unroll
    for (int k = 0; k < 9; k++) {
        float2 wp = *reinterpret_cast<const float2*>(&g_wf[k * COUT + c0]);
        wa[k] = wp.x;
        wb[k] = wp.y;
    }
    const float2 bp = *reinterpret_cast<const float2*>(&g_bf[c0]);

    for (int p = gw; p < n; p += nw) {
        const float4 A = g_nb0[p];
        const float4 B = g_nb1[p];
        const float  s8 = g_nb8[p];

        float o0 = bp.x, o1 = bp.y;
        o0 = fmaf(A.x, wa[0], o0);  o1 = fmaf(A.x, wb[0], o1);
        o0 = fmaf(A.y, wa[1], o0);  o1 = fmaf(A.y, wb[1], o1);
        o0 = fmaf(A.z, wa[2], o0);  o1 = fmaf(A.z, wb[2], o1);
        o0 = fmaf(A.w, wa[3], o0);  o1 = fmaf(A.w, wb[3], o1);
        o0 = fmaf(B.x, wa[4], o0);  o1 = fmaf(B.x, wb[4], o1);
        o0 = fmaf(B.y, wa[5], o0);  o1 = fmaf(B.y, wb[5], o1);
        o0 = fmaf(B.z, wa[6], o0);  o1 = fmaf(B.z, wb[6], o1);
        o0 = fmaf(B.w, wa[7], o0);  o1 = fmaf(B.w, wb[7], o1);
        o0 = fmaf(s8,  wa[8], o0);  o1 = fmaf(s8,  wb[8], o1);

        o0 = fmaxf(o0, 0.f);
        o1 = fmaxf(o1, 0.f);
        out[(size_t)p * 32 + lane] = make_float2(o0, o1);
    }
}

// ---------------------------------------------------------------------------
// Launch: inputs are feats[N,1] f32, weight[9,1,64] f32, gamma[64], beta[64],
//         coords[N,2] i32. Output: [N,64] f32.
// ---------------------------------------------------------------------------
extern "C" void kernel_launch(void* const* d_in, const int* in_sizes, int n_in,
                              void* d_out, int out_size) {
    const float* feats  = (const float*)d_in[0];
    const float* weight = (const float*)d_in[1];
    const float* gamma  = (const float*)d_in[2];
    const float* beta   = (const float*)d_in[3];
    const int2*  coords = (const int2*)d_in[4];
    const int n = in_sizes[0];   // N (C_IN = 1)

    k_zero_grid<<<2055, 256>>>();
    k_scatter<<<(n + 255) / 256, 256>>>(coords, feats, n);
    k_gather_stats<<<STATS_BLOCKS, 256>>>(coords, n);
    k_finalize<<<1, 128>>>(weight, gamma, beta, n);
    k_output<<<1184, 256>>>((float2*)d_out, n);
}

// round 2
// speedup vs baseline: 1.3400x; 1.3400x over previous
#include <cuda_runtime.h>

// Problem constants (fixed by the dataset)
#define HH   1024
#define WW   2048
#define GW   (WW + 2)        // padded grid width  = 2050
#define GH   (HH + 2)        // padded grid height = 1026
#define GSZ  (GH * GW)       // 2,103,300 floats (divisible by 4)
#define COUT 64
#define BN_EPS 1e-5f
#define STATS_BLOCKS 296

// Scratch (static __device__ arrays — no allocation)
__device__ float  g_grid[GSZ];                     // ~8.4 MB padded dense grid (L2-resident)
__device__ float  g_part[STATS_BLOCKS * 54];       // per-block stat partials
__device__ float  g_wf[9 * COUT];                  // BN-folded weights
__device__ float  g_bf[COUT];                      // BN-folded bias

// ---------------------------------------------------------------------------
// K0: zero the padded grid (float4 stream)
// ---------------------------------------------------------------------------
__global__ void k_zero_grid() {
    const int n4 = GSZ / 4;
    float4 z = make_float4(0.f, 0.f, 0.f, 0.f);
    for (int j = blockIdx.x * blockDim.x + threadIdx.x; j < n4;
         j += gridDim.x * blockDim.x)
        reinterpret_cast<float4*>(g_grid)[j] = z;
}

// ---------------------------------------------------------------------------
// K1: scatter active features into the padded grid
// ---------------------------------------------------------------------------
__global__ void k_scatter(const int2* __restrict__ coords,
                          const float* __restrict__ feats, int n) {
    int i = blockIdx.x * blockDim.x + threadIdx.x;
    if (i < n) {
        int2 c = coords[i];                        // c.x = y, c.y = x
        g_grid[(c.x + 1) * GW + (c.y + 1)] = feats[i];
    }
}

// ---------------------------------------------------------------------------
// K2: per-point gather of the 9 neighbors from the L2-resident grid;
//     accumulate sum9[9] + upper-tri second-moment M[45] into per-block
//     partials (deterministic — no float atomics). No nb packing.
// ---------------------------------------------------------------------------
__global__ __launch_bounds__(256) void k_gather_stats(
        const int2* __restrict__ coords, int n) {
    float acc[54];
#pragma unroll
    for (int i = 0; i < 54; i++) acc[i] = 0.f;

    const int tid    = blockIdx.x * blockDim.x + threadIdx.x;
    const int stride = gridDim.x * blockDim.x;

    for (int p = tid; p < n; p += stride) {
        int2 c = coords[p];
        const float* base = g_grid + c.x * GW + c.y;   // top-left neighbor in padded grid
        float s[9];
#pragma unroll
        for (int r = 0; r < 3; r++)
#pragma unroll
            for (int q = 0; q < 3; q++)
                s[r * 3 + q] = __ldg(base + r * GW + q);

#pragma unroll
        for (int k = 0; k < 9; k++) acc[k] += s[k];
        int idx = 9;
#pragma unroll
        for (int j = 0; j < 9; j++)
#pragma unroll
            for (int k = j; k < 9; k++) acc[idx++] += s[j] * s[k];
    }

    // block reduction: warp shfl -> shared -> per-block partial
    __shared__ float red[54 * 8];
    const int w = threadIdx.x >> 5, lane = threadIdx.x & 31;
#pragma unroll
    for (int i = 0; i < 54; i++) {
        float v = acc[i];
#pragma unroll
        for (int o = 16; o; o >>= 1) v += __shfl_xor_sync(0xffffffffu, v, o);
        if (lane == 0) red[i * 8 + w] = v;
    }
    __syncthreads();
    if (threadIdx.x < 54) {
        float v = 0.f;
#pragma unroll
        for (int ww = 0; ww < 8; ww++) v += red[threadIdx.x * 8 + ww];
        g_part[blockIdx.x * 54 + threadIdx.x] = v;
    }
}

// ---------------------------------------------------------------------------
// K3: parallel partial reduction (16 lanes per stat) + analytic BN fold:
//     W'[k,c] = W[k,c]*scale_c ; b'[c] = beta_c - mean_c*scale_c
// ---------------------------------------------------------------------------
__global__ __launch_bounds__(1024) void k_finalize(
        const float* __restrict__ weight,   // [9,1,64]
        const float* __restrict__ gamma,
        const float* __restrict__ beta, int n) {
    __shared__ float st[64];
    const int t = threadIdx.x;          // 1024 threads
    const int g = t >> 4;               // stat index (0..63, 54 used)
    const int j = t & 15;               // sub-lane within stat group

    float v = 0.f;
    if (g < 54)
        for (int b = j; b < STATS_BLOCKS; b += 16)
            v += g_part[b * 54 + g];
#pragma unroll
    for (int o = 8; o; o >>= 1) v += __shfl_xor_sync(0xffffffffu, v, o);
    if (j == 0 && g < 54) st[g] = v;
    __syncthreads();

    if (t < COUT) {
        float w[9];
#pragma unroll
        for (int k = 0; k < 9; k++) w[k] = weight[k * COUT + t];
        const float invn = 1.f / (float)n;

        float mean = 0.f;
#pragma unroll
        for (int k = 0; k < 9; k++) mean += st[k] * w[k];
        mean *= invn;

        float q = 0.f;
        int idx = 9;
#pragma unroll
        for (int jj = 0; jj < 9; jj++)
#pragma unroll
            for (int k = jj; k < 9; k++) {
                float term = st[idx++] * w[jj] * w[k];
                q += (jj == k) ? term : 2.f * term;
            }
        float var   = fmaxf(q * invn - mean * mean, 0.f);
        float scale = gamma[t] * rsqrtf(var + BN_EPS);
#pragma unroll
        for (int k = 0; k < 9; k++) g_wf[k * COUT + t] = w[k] * scale;
        g_bf[t] = beta[t] - mean * scale;
    }
}

// ---------------------------------------------------------------------------
// K4: output pass. One warp per point; lane l computes channels 2l, 2l+1 and
//     writes a float2 -> each warp writes one fully-coalesced 256 B row.
//     Neighbor values gathered directly from the L2-resident grid via
//     lane-uniform broadcast loads. Streaming stores keep the grid hot in L2.
// ---------------------------------------------------------------------------
__global__ __launch_bounds__(256) void k_output(
        const int2* __restrict__ coords, float2* __restrict__ out, int n) {
    const int lane = threadIdx.x & 31;
    const int gw   = (blockIdx.x * blockDim.x + threadIdx.x) >> 5;
    const int nw   = (gridDim.x * blockDim.x) >> 5;
    const int c0   = lane * 2;

    float wa[9], wb[9];
#pragma unroll
    for (int k = 0; k < 9; k++) {
        float2 wp = *reinterpret_cast<const float2*>(&g_wf[k * COUT + c0]);
        wa[k] = wp.x;
        wb[k] = wp.y;
    }
    const float2 bp = *reinterpret_cast<const float2*>(&g_bf[c0]);

    for (int p = gw; p < n; p += nw) {
        const int2 c = __ldg(&coords[p]);
        const float* base = g_grid + c.x * GW + c.y;

        float s[9];
#pragma unroll
        for (int r = 0; r < 3; r++)
#pragma unroll
            for (int q = 0; q < 3; q++)
                s[r * 3 + q] = __ldg(base + r * GW + q);

        float o0 = bp.x, o1 = bp.y;
#pragma unroll
        for (int k = 0; k < 9; k++) {
            o0 = fmaf(s[k], wa[k], o0);
            o1 = fmaf(s[k], wb[k], o1);
        }
        o0 = fmaxf(o0, 0.f);
        o1 = fmaxf(o1, 0.f);
        __stcs(&out[(size_t)p * 32 + lane], make_float2(o0, o1));
    }
}

// ---------------------------------------------------------------------------
// Launch: inputs are feats[N,1] f32, weight[9,1,64] f32, gamma[64], beta[64],
//         coords[N,2] i32. Output: [N,64] f32.
// ---------------------------------------------------------------------------
extern "C" void kernel_launch(void* const* d_in, const int* in_sizes, int n_in,
                              void* d_out, int out_size) {
    const float* feats  = (const float*)d_in[0];
    const float* weight = (const float*)d_in[1];
    const float* gamma  = (const float*)d_in[2];
    const float* beta   = (const float*)d_in[3];
    const int2*  coords = (const int2*)d_in[4];
    const int n = in_sizes[0];   // N (C_IN = 1)

    k_zero_grid<<<2055, 256>>>();
    k_scatter<<<(n + 255) / 256, 256>>>(coords, feats, n);
    k_gather_stats<<<STATS_BLOCKS, 256>>>(coords, n);
    k_finalize<<<1, 1024>>>(weight, gamma, beta, n);
    k_output<<<1184, 256>>>(coords, (float2*)d_out, n);
}

// round 3
// speedup vs baseline: 1.8776x; 1.4012x over previous
#include <cuda_runtime.h>

// Problem constants (fixed by the dataset)
#define HH   1024
#define WW   2048
#define GW   (WW + 2)        // padded grid width  = 2050
#define GH   (HH + 2)        // padded grid height = 1026
#define GSZ  (GH * GW)       // 2,103,300 floats (divisible by 4)
#define COUT 64
#define BN_EPS 1e-5f
#define STATS_BLOCKS 296
#define TILE 256

// Scratch (static __device__ arrays — no allocation)
__device__ float  g_grid[GSZ];                     // ~8.4 MB padded dense grid (L2-resident)
__device__ float  g_part[STATS_BLOCKS * 54];       // per-block stat partials
__device__ float  g_wf[9 * COUT];                  // BN-folded weights
__device__ float  g_bf[COUT];                      // BN-folded bias
__device__ int    g_ctr;                           // last-block-done counter

// ---------------------------------------------------------------------------
// K0: zero the padded grid (float4 stream) + reset the stats counter
// ---------------------------------------------------------------------------
__global__ void k_zero_grid() {
    if (blockIdx.x == 0 && threadIdx.x == 0) g_ctr = 0;
    const int n4 = GSZ / 4;
    float4 z = make_float4(0.f, 0.f, 0.f, 0.f);
    for (int j = blockIdx.x * blockDim.x + threadIdx.x; j < n4;
         j += gridDim.x * blockDim.x)
        reinterpret_cast<float4*>(g_grid)[j] = z;
}

// ---------------------------------------------------------------------------
// K1: scatter active features into the padded grid
// ---------------------------------------------------------------------------
__global__ void k_scatter(const int2* __restrict__ coords,
                          const float* __restrict__ feats, int n) {
    int i = blockIdx.x * blockDim.x + threadIdx.x;
    if (i < n) {
        int2 c = coords[i];                        // c.x = y, c.y = x
        g_grid[(c.x + 1) * GW + (c.y + 1)] = feats[i];
    }
}

// ---------------------------------------------------------------------------
// K2: per-point gather of the 9 neighbors from the L2-resident grid;
//     accumulate sum9[9] + upper-tri second-moment M[45] deterministically.
//     The LAST block to finish reduces all partials and folds BN into the
//     conv weights (no separate finalize launch).
// ---------------------------------------------------------------------------
__global__ __launch_bounds__(256) void k_gather_stats(
        const int2* __restrict__ coords,
        const float* __restrict__ weight,   // [9,1,64]
        const float* __restrict__ gamma,
        const float* __restrict__ beta, int n) {
    float acc[54];
#pragma unroll
    for (int i = 0; i < 54; i++) acc[i] = 0.f;

    const int tid    = blockIdx.x * blockDim.x + threadIdx.x;
    const int stride = gridDim.x * blockDim.x;

    for (int p = tid; p < n; p += stride) {
        int2 c = coords[p];
        const float* base = g_grid + c.x * GW + c.y;   // top-left neighbor
        float s[9];
#pragma unroll
        for (int r = 0; r < 3; r++)
#pragma unroll
            for (int q = 0; q < 3; q++)
                s[r * 3 + q] = __ldg(base + r * GW + q);

#pragma unroll
        for (int k = 0; k < 9; k++) acc[k] += s[k];
        int idx = 9;
#pragma unroll
        for (int j = 0; j < 9; j++)
#pragma unroll
            for (int k = j; k < 9; k++) acc[idx++] += s[j] * s[k];
    }

    // block reduction: warp shfl -> shared -> per-block partial
    __shared__ float red[54 * 8];
    const int w = threadIdx.x >> 5, lane = threadIdx.x & 31;
#pragma unroll
    for (int i = 0; i < 54; i++) {
        float v = acc[i];
#pragma unroll
        for (int o = 16; o; o >>= 1) v += __shfl_xor_sync(0xffffffffu, v, o);
        if (lane == 0) red[i * 8 + w] = v;
    }
    __syncthreads();
    if (threadIdx.x < 54) {
        float v = 0.f;
#pragma unroll
        for (int ww = 0; ww < 8; ww++) v += red[threadIdx.x * 8 + ww];
        g_part[blockIdx.x * 54 + threadIdx.x] = v;
    }

    // ---- last-block-done: reduce partials + fold BN into weights ----
    __shared__ bool is_last;
    __threadfence();
    if (threadIdx.x == 0) {
        int prev = atomicAdd(&g_ctr, 1);
        is_last = (prev == gridDim.x - 1);
    }
    __syncthreads();
    if (!is_last) return;

    __shared__ float st[64];
    {
        const int t = threadIdx.x;      // 256 threads
        const int g = t >> 2;           // stat index (0..63, 54 used)
        const int j = t & 3;            // sub-lane within stat group
        float v = 0.f;
        if (g < 54)
            for (int b = j; b < STATS_BLOCKS; b += 4)
                v += g_part[b * 54 + g];
        v += __shfl_xor_sync(0xffffffffu, v, 1);
        v += __shfl_xor_sync(0xffffffffu, v, 2);
        if (j == 0 && g < 54) st[g] = v;
    }
    __syncthreads();

    if (threadIdx.x < COUT) {
        const int t = threadIdx.x;
        float wv[9];
#pragma unroll
        for (int k = 0; k < 9; k++) wv[k] = weight[k * COUT + t];
        const float invn = 1.f / (float)n;

        float mean = 0.f;
#pragma unroll
        for (int k = 0; k < 9; k++) mean += st[k] * wv[k];
        mean *= invn;

        float q = 0.f;
        int idx = 9;
#pragma unroll
        for (int jj = 0; jj < 9; jj++)
#pragma unroll
            for (int k = jj; k < 9; k++) {
                float term = st[idx++] * wv[jj] * wv[k];
                q += (jj == k) ? term : 2.f * term;
            }
        float var   = fmaxf(q * invn - mean * mean, 0.f);
        float scale = gamma[t] * rsqrtf(var + BN_EPS);
#pragma unroll
        for (int k = 0; k < 9; k++) g_wf[k * COUT + t] = wv[k] * scale;
        g_bf[t] = beta[t] - mean * scale;
    }
}

// ---------------------------------------------------------------------------
// K4: output pass, two-phase per 256-point tile.
//     Phase A: each thread gathers the 9 neighbors of ITS OWN point
//              (per-thread parallel LDG — 9 instructions per warp serve
//              32 points) and stages them in smem (stride-9 rows:
//              conflict-free since gcd(9,32)=1).
//     Phase B: warp-per-point — 9 broadcast LDS + 18 FMA per point; lane l
//              computes channels 2l,2l+1 and writes a coalesced 256 B row
//              with streaming stores (keeps the grid hot in L2).
// ---------------------------------------------------------------------------
__global__ __launch_bounds__(256) void k_output(
        const int2* __restrict__ coords, float2* __restrict__ out, int n) {
    __shared__ float sm[TILE * 9];
    const int tid  = threadIdx.x;
    const int lane = tid & 31;
    const int wid  = tid >> 5;
    const int c0   = lane * 2;

    float wa[9], wb[9];
#pragma unroll
    for (int k = 0; k < 9; k++) {
        float2 wp = *reinterpret_cast<const float2*>(&g_wf[k * COUT + c0]);
        wa[k] = wp.x;
        wb[k] = wp.y;
    }
    const float2 bp = *reinterpret_cast<const float2*>(&g_bf[c0]);

    const int ntiles = (n + TILE - 1) / TILE;
    for (int tile = blockIdx.x; tile < ntiles; tile += gridDim.x) {
        const int base_p = tile * TILE;

        // Phase A: per-thread gather into smem
        const int p = base_p + tid;
        if (p < n) {
            const int2 c = __ldg(&coords[p]);
            const float* base = g_grid + c.x * GW + c.y;
#pragma unroll
            for (int r = 0; r < 3; r++)
#pragma unroll
                for (int q = 0; q < 3; q++)
                    sm[tid * 9 + r * 3 + q] = __ldg(base + r * GW + q);
        }
        __syncthreads();

        // Phase B: warp-per-point compute + coalesced row store
        const int npts = min(TILE, n - base_p);
        const int jend = min(wid * 32 + 32, npts);
#pragma unroll 2
        for (int j = wid * 32; j < jend; j++) {
            float s[9];
#pragma unroll
            for (int k = 0; k < 9; k++) s[k] = sm[j * 9 + k];

            float o0 = bp.x, o1 = bp.y;
#pragma unroll
            for (int k = 0; k < 9; k++) {
                o0 = fmaf(s[k], wa[k], o0);
                o1 = fmaf(s[k], wb[k], o1);
            }
            o0 = fmaxf(o0, 0.f);
            o1 = fmaxf(o1, 0.f);
            __stcs(&out[(size_t)(base_p + j) * 32 + lane],
                   make_float2(o0, o1));
        }
        __syncthreads();
    }
}

// ---------------------------------------------------------------------------
// Launch: inputs are feats[N,1] f32, weight[9,1,64] f32, gamma[64], beta[64],
//         coords[N,2] i32. Output: [N,64] f32.
// ---------------------------------------------------------------------------
extern "C" void kernel_launch(void* const* d_in, const int* in_sizes, int n_in,
                              void* d_out, int out_size) {
    const float* feats  = (const float*)d_in[0];
    const float* weight = (const float*)d_in[1];
    const float* gamma  = (const float*)d_in[2];
    const float* beta   = (const float*)d_in[3];
    const int2*  coords = (const int2*)d_in[4];
    const int n = in_sizes[0];   // N (C_IN = 1)

    k_zero_grid<<<2055, 256>>>();
    k_scatter<<<(n + 255) / 256, 256>>>(coords, feats, n);
    k_gather_stats<<<STATS_BLOCKS, 256>>>(coords, weight, gamma, beta, n);
    k_output<<<1480, 256>>>(coords, (float2*)d_out, n);
}

// round 4
// speedup vs baseline: 1.9163x; 1.0206x over previous
#include <cuda_runtime.h>

// Problem constants (fixed by the dataset)
#define HH   1024
#define WW   2048
#define GW   (WW + 2)        // padded grid width  = 2050
#define GH   (HH + 2)        // padded grid height = 1026
#define GSZ  (GH * GW)       // 2,103,300 floats (divisible by 4)
#define NPIX (HH * WW)       // 2,097,152
#define COUT 64
#define BN_EPS 1e-5f
#define STATS_BLOCKS 592
#define TILE 256

// Scratch (static __device__ arrays — no allocation)
__device__ float         g_grid[GSZ];                // ~8.4 MB padded dense grid (L2-resident)
__device__ unsigned char g_mask[NPIX];               // 2 MB active-pixel mask
__device__ float         g_part[STATS_BLOCKS * 54];  // per-block stat partials
__device__ float         g_wf[9 * COUT];             // BN-folded weights
__device__ float         g_bf[COUT];                 // BN-folded bias
__device__ int           g_ctr;                      // last-block-done counter

// ---------------------------------------------------------------------------
// K0: zero the padded grid + mask (vector stream) + reset the stats counter
// ---------------------------------------------------------------------------
__global__ void k_zero() {
    if (blockIdx.x == 0 && threadIdx.x == 0) g_ctr = 0;
    const int n4g = GSZ / 4;           // 525,825 float4
    const int n4m = NPIX / 16;         // 131,072 int4
    float4 z = make_float4(0.f, 0.f, 0.f, 0.f);
    int4   zi = make_int4(0, 0, 0, 0);
    const int tid = blockIdx.x * blockDim.x + threadIdx.x;
    const int str = gridDim.x * blockDim.x;
    for (int j = tid; j < n4g; j += str)
        reinterpret_cast<float4*>(g_grid)[j] = z;
    for (int j = tid; j < n4m; j += str)
        reinterpret_cast<int4*>(g_mask)[j] = zi;
}

// ---------------------------------------------------------------------------
// K1: scatter active features into the padded grid + set mask
// ---------------------------------------------------------------------------
__global__ void k_scatter(const int2* __restrict__ coords,
                          const float* __restrict__ feats, int n) {
    int i = blockIdx.x * blockDim.x + threadIdx.x;
    if (i < n) {
        int2 c = coords[i];                        // c.x = y, c.y = x
        g_grid[(c.x + 1) * GW + (c.y + 1)] = feats[i];
        g_mask[c.x * WW + c.y] = 1;
    }
}

// ---------------------------------------------------------------------------
// K2: DENSE row-major stats scan. For every pixel q (coalesced), taps are
//     multiplied by mask(q) in {0,1} so inactive centers contribute nothing
//     (m^2 == m). Accumulates sum9[9] + upper-tri second-moment M[45] into
//     fixed-order per-block partials (deterministic). The LAST block reduces
//     all partials and folds BN into the conv weights (no extra launch).
// ---------------------------------------------------------------------------
__global__ __launch_bounds__(256) void k_stats(
        const float* __restrict__ weight,   // [9,1,64]
        const float* __restrict__ gamma,
        const float* __restrict__ beta, int n) {
    float acc[54];
#pragma unroll
    for (int i = 0; i < 54; i++) acc[i] = 0.f;

    const int tid    = blockIdx.x * blockDim.x + threadIdx.x;
    const int stride = gridDim.x * blockDim.x;

    for (int q = tid; q < NPIX; q += stride) {
        const int y = q >> 11;           // WW = 2048
        const int x = q & (WW - 1);
        const float m = (float)g_mask[q];
        const float* base = g_grid + y * GW + x;   // top-left tap in padded grid
        float s[9];
#pragma unroll
        for (int r = 0; r < 3; r++)
#pragma unroll
            for (int c = 0; c < 3; c++)
                s[r * 3 + c] = base[r * GW + c] * m;

#pragma unroll
        for (int k = 0; k < 9; k++) acc[k] += s[k];
        int idx = 9;
#pragma unroll
        for (int j = 0; j < 9; j++)
#pragma unroll
            for (int k = j; k < 9; k++) acc[idx++] += s[j] * s[k];
    }

    // block reduction: warp shfl -> shared -> per-block partial
    __shared__ float red[54 * 8];
    const int w = threadIdx.x >> 5, lane = threadIdx.x & 31;
#pragma unroll
    for (int i = 0; i < 54; i++) {
        float v = acc[i];
#pragma unroll
        for (int o = 16; o; o >>= 1) v += __shfl_xor_sync(0xffffffffu, v, o);
        if (lane == 0) red[i * 8 + w] = v;
    }
    __syncthreads();
    if (threadIdx.x < 54) {
        float v = 0.f;
#pragma unroll
        for (int ww = 0; ww < 8; ww++) v += red[threadIdx.x * 8 + ww];
        g_part[blockIdx.x * 54 + threadIdx.x] = v;
    }

    // ---- last-block-done: reduce partials + fold BN into weights ----
    __shared__ bool is_last;
    __threadfence();
    if (threadIdx.x == 0) {
        int prev = atomicAdd(&g_ctr, 1);
        is_last = (prev == gridDim.x - 1);
    }
    __syncthreads();
    if (!is_last) return;

    __shared__ float st[64];
    {
        const int t = threadIdx.x;      // 256 threads
        const int g = t >> 2;           // stat index (0..63, 54 used)
        const int j = t & 3;            // sub-lane within stat group
        float v = 0.f;
        if (g < 54)
            for (int b = j; b < STATS_BLOCKS; b += 4)
                v += g_part[b * 54 + g];
        v += __shfl_xor_sync(0xffffffffu, v, 1);
        v += __shfl_xor_sync(0xffffffffu, v, 2);
        if (j == 0 && g < 54) st[g] = v;
    }
    __syncthreads();

    if (threadIdx.x < COUT) {
        const int t = threadIdx.x;
        float wv[9];
#pragma unroll
        for (int k = 0; k < 9; k++) wv[k] = weight[k * COUT + t];
        const float invn = 1.f / (float)n;

        float mean = 0.f;
#pragma unroll
        for (int k = 0; k < 9; k++) mean += st[k] * wv[k];
        mean *= invn;

        float q = 0.f;
        int idx = 9;
#pragma unroll
        for (int jj = 0; jj < 9; jj++)
#pragma unroll
            for (int k = jj; k < 9; k++) {
                float term = st[idx++] * wv[jj] * wv[k];
                q += (jj == k) ? term : 2.f * term;
            }
        float var   = fmaxf(q * invn - mean * mean, 0.f);
        float scale = gamma[t] * rsqrtf(var + BN_EPS);
#pragma unroll
        for (int k = 0; k < 9; k++) g_wf[k * COUT + t] = wv[k] * scale;
        g_bf[t] = beta[t] - mean * scale;
    }
}

// ---------------------------------------------------------------------------
// K4: output pass, two-phase per 256-point tile.
//     Phase A: each thread gathers the 9 taps of ITS OWN point and stages
//              them as 3 aligned float4 (stride 12 floats; quarter-warp
//              STS.128 banks all distinct -> conflict-free).
//     Phase B: HALF-warp per point, lane computes 4 channels (float4).
//              Per 2 points: 3 broadcast LDS.128 + 72 FMA + 1 fully
//              coalesced STG.128 (two 256 B rows). Streaming stores keep
//              the grid hot in L2.
// ---------------------------------------------------------------------------
__global__ __launch_bounds__(256) void k_output(
        const int2* __restrict__ coords, float4* __restrict__ out, int n) {
    __shared__ float4 sm[TILE * 3];
    const int tid  = threadIdx.x;
    const int lane = tid & 31;
    const int wid  = tid >> 5;
    const int h    = lane >> 4;        // half-warp id (0/1)
    const int cl   = lane & 15;        // float4 channel group (c = 4*cl)

    // Preload BN-folded weights for this lane's 4 channels
    float4 w4[9];
#pragma unroll
    for (int k = 0; k < 9; k++)
        w4[k] = reinterpret_cast<const float4*>(g_wf)[k * 16 + cl];
    const float4 b4 = reinterpret_cast<const float4*>(g_bf)[cl];

    const int ntiles = (n + TILE - 1) / TILE;
    for (int tile = blockIdx.x; tile < ntiles; tile += gridDim.x) {
        const int base_p = tile * TILE;

        // Phase A: per-thread gather into smem
        const int p = base_p + tid;
        if (p < n) {
            const int2 c = __ldg(&coords[p]);
            const float* base = g_grid + c.x * GW + c.y;
            float s[9];
#pragma unroll
            for (int r = 0; r < 3; r++)
#pragma unroll
                for (int q = 0; q < 3; q++)
                    s[r * 3 + q] = __ldg(base + r * GW + q);
            sm[tid * 3 + 0] = make_float4(s[0], s[1], s[2], s[3]);
            sm[tid * 3 + 1] = make_float4(s[4], s[5], s[6], s[7]);
            sm[tid * 3 + 2] = make_float4(s[8], 0.f, 0.f, 0.f);
        }
        __syncthreads();

        // Phase B: half-warp per point, 2 points per warp-iteration
        const int npts = min(TILE, n - base_p);
        const int jend = min(wid * 32 + 32, npts);
        for (int jj = wid * 32; jj < jend; jj += 2) {
            const int j = jj + h;
            if (j < npts) {
                const float4 A = sm[j * 3 + 0];
                const float4 B = sm[j * 3 + 1];
                const float  s8 = sm[j * 3 + 2].x;

                float4 o = b4;
                o.x = fmaf(A.x, w4[0].x, o.x); o.y = fmaf(A.x, w4[0].y, o.y);
                o.z = fmaf(A.x, w4[0].z, o.z); o.w = fmaf(A.x, w4[0].w, o.w);
                o.x = fmaf(A.y, w4[1].x, o.x); o.y = fmaf(A.y, w4[1].y, o.y);
                o.z = fmaf(A.y, w4[1].z, o.z); o.w = fmaf(A.y, w4[1].w, o.w);
                o.x = fmaf(A.z, w4[2].x, o.x); o.y = fmaf(A.z, w4[2].y, o.y);
                o.z = fmaf(A.z, w4[2].z, o.z); o.w = fmaf(A.z, w4[2].w, o.w);
                o.x = fmaf(A.w, w4[3].x, o.x); o.y = fmaf(A.w, w4[3].y, o.y);
                o.z = fmaf(A.w, w4[3].z, o.z); o.w = fmaf(A.w, w4[3].w, o.w);
                o.x = fmaf(B.x, w4[4].x, o.x); o.y = fmaf(B.x, w4[4].y, o.y);
                o.z = fmaf(B.x, w4[4].z, o.z); o.w = fmaf(B.x, w4[4].w, o.w);
                o.x = fmaf(B.y, w4[5].x, o.x); o.y = fmaf(B.y, w4[5].y, o.y);
                o.z = fmaf(B.y, w4[5].z, o.z); o.w = fmaf(B.y, w4[5].w, o.w);
                o.x = fmaf(B.z, w4[6].x, o.x); o.y = fmaf(B.z, w4[6].y, o.y);
                o.z = fmaf(B.z, w4[6].z, o.z); o.w = fmaf(B.z, w4[6].w, o.w);
                o.x = fmaf(B.w, w4[7].x, o.x); o.y = fmaf(B.w, w4[7].y, o.y);
                o.z = fmaf(B.w, w4[7].z, o.z); o.w = fmaf(B.w, w4[7].w, o.w);
                o.x = fmaf(s8,  w4[8].x, o.x); o.y = fmaf(s8,  w4[8].y, o.y);
                o.z = fmaf(s8,  w4[8].z, o.z); o.w = fmaf(s8,  w4[8].w, o.w);

                o.x = fmaxf(o.x, 0.f); o.y = fmaxf(o.y, 0.f);
                o.z = fmaxf(o.z, 0.f); o.w = fmaxf(o.w, 0.f);
                __stcs(&out[(size_t)(base_p + j) * 16 + cl], o);
            }
        }
        __syncthreads();
    }
}

// ---------------------------------------------------------------------------
// Launch: inputs are feats[N,1] f32, weight[9,1,64] f32, gamma[64], beta[64],
//         coords[N,2] i32. Output: [N,64] f32.
// ---------------------------------------------------------------------------
extern "C" void kernel_launch(void* const* d_in, const int* in_sizes, int n_in,
                              void* d_out, int out_size) {
    const float* feats  = (const float*)d_in[0];
    const float* weight = (const float*)d_in[1];
    const float* gamma  = (const float*)d_in[2];
    const float* beta   = (const float*)d_in[3];
    const int2*  coords = (const int2*)d_in[4];
    const int n = in_sizes[0];   // N (C_IN = 1)

    k_zero<<<1480, 256>>>();
    k_scatter<<<(n + 255) / 256, 256>>>(coords, feats, n);
    k_stats<<<STATS_BLOCKS, 256>>>(weight, gamma, beta, n);
    k_output<<<1480, 256>>>(coords, (float4*)d_out, n);
}

// round 5
// speedup vs baseline: 2.2392x; 1.1685x over previous
#include <cuda_runtime.h>

// Problem constants (fixed by the dataset)
#define HH   1024
#define WW   2048
#define GW2  2052            // padded row stride (multiple of 4 for aligned float4)
#define GH   (HH + 2)        // padded grid height = 1026
#define GSZ  (GH * GW2)      // 2,105,352 floats
#define NPIX (HH * WW)       // 2,097,152
#define COUT 64
#define BN_EPS 1e-5f
#define STATS_BLOCKS 592
#define TILE 256

// Scratch (static __device__ arrays — no allocation)
__device__ float g_grid[GSZ];                // ~8.4 MB padded dense grid (L2-resident)
__device__ int   g_idx[NPIX];                // 8 MB pixel -> output-row index (-1 = empty)
__device__ float g_part[STATS_BLOCKS * 54];  // per-block stat partials
__device__ float g_wf[9 * COUT];             // BN-folded weights
__device__ float g_bf[COUT];                 // BN-folded bias
__device__ int   g_ctr;                      // last-block-done counter

// ---------------------------------------------------------------------------
// K0: zero the padded grid, fill idx with -1, reset the stats counter
// ---------------------------------------------------------------------------
__global__ void k_zero() {
    if (blockIdx.x == 0 && threadIdx.x == 0) g_ctr = 0;
    const int n4g = GSZ / 4;           // 526,338 float4
    const int n4i = NPIX / 4;          // 524,288 int4
    float4 z  = make_float4(0.f, 0.f, 0.f, 0.f);
    int4   mi = make_int4(-1, -1, -1, -1);
    const int tid = blockIdx.x * blockDim.x + threadIdx.x;
    const int str = gridDim.x * blockDim.x;
    for (int j = tid; j < n4g; j += str)
        reinterpret_cast<float4*>(g_grid)[j] = z;
    for (int j = tid; j < n4i; j += str)
        reinterpret_cast<int4*>(g_idx)[j] = mi;
}

// ---------------------------------------------------------------------------
// K1: scatter active features into the padded grid + record output row index
// ---------------------------------------------------------------------------
__global__ void k_scatter(const int2* __restrict__ coords,
                          const float* __restrict__ feats, int n) {
    int i = blockIdx.x * blockDim.x + threadIdx.x;
    if (i < n) {
        int2 c = coords[i];                        // c.x = y, c.y = x
        g_grid[(c.x + 1) * GW2 + (c.y + 1)] = feats[i];
        g_idx[c.x * WW + c.y] = i;
    }
}

// ---------------------------------------------------------------------------
// K2: DENSE vectorized stats scan — each thread handles 4 consecutive pixels
//     with 6 aligned LDG.128 (3 rows x 2 float4) + 1 int4 (idx as mask).
//     Accumulates sum9[9] + upper-tri second moment M[45] in fixed order
//     (deterministic). LAST block reduces partials + folds BN into weights.
// ---------------------------------------------------------------------------
__global__ __launch_bounds__(256) void k_stats(
        const float* __restrict__ weight,   // [9,1,64]
        const float* __restrict__ gamma,
        const float* __restrict__ beta, int n) {
    float acc[54];
#pragma unroll
    for (int i = 0; i < 54; i++) acc[i] = 0.f;

    const int tid    = blockIdx.x * blockDim.x + threadIdx.x;
    const int stride = gridDim.x * blockDim.x;
    const int nquad  = NPIX / 4;

    for (int Q = tid; Q < nquad; Q += stride) {
        const int q = Q * 4;
        const int y = q >> 11;           // WW = 2048
        const int x = q & (WW - 1);      // multiple of 4
        const float* rb = g_grid + y * GW2 + x;   // row base, 16B-aligned

        float4 a0 = *reinterpret_cast<const float4*>(rb);
        float4 a1 = *reinterpret_cast<const float4*>(rb + 4);
        float4 b0 = *reinterpret_cast<const float4*>(rb + GW2);
        float4 b1 = *reinterpret_cast<const float4*>(rb + GW2 + 4);
        float4 c0 = *reinterpret_cast<const float4*>(rb + 2 * GW2);
        float4 c1 = *reinterpret_cast<const float4*>(rb + 2 * GW2 + 4);
        int4 iv = *reinterpret_cast<const int4*>(g_idx + q);

        float r0[8] = {a0.x, a0.y, a0.z, a0.w, a1.x, a1.y, a1.z, a1.w};
        float r1[8] = {b0.x, b0.y, b0.z, b0.w, b1.x, b1.y, b1.z, b1.w};
        float r2[8] = {c0.x, c0.y, c0.z, c0.w, c1.x, c1.y, c1.z, c1.w};
        float m[4]  = {iv.x >= 0 ? 1.f : 0.f, iv.y >= 0 ? 1.f : 0.f,
                       iv.z >= 0 ? 1.f : 0.f, iv.w >= 0 ? 1.f : 0.f};

#pragma unroll
        for (int i = 0; i < 4; i++) {
            float s[9];
#pragma unroll
            for (int t = 0; t < 3; t++) {
                s[0 + t] = r0[i + t] * m[i];
                s[3 + t] = r1[i + t] * m[i];
                s[6 + t] = r2[i + t] * m[i];
            }
#pragma unroll
            for (int k = 0; k < 9; k++) acc[k] += s[k];
            int idx = 9;
#pragma unroll
            for (int j = 0; j < 9; j++)
#pragma unroll
                for (int k = j; k < 9; k++) acc[idx++] += s[j] * s[k];
        }
    }

    // block reduction: warp shfl -> shared -> per-block partial
    __shared__ float red[54 * 8];
    const int w = threadIdx.x >> 5, lane = threadIdx.x & 31;
#pragma unroll
    for (int i = 0; i < 54; i++) {
        float v = acc[i];
#pragma unroll
        for (int o = 16; o; o >>= 1) v += __shfl_xor_sync(0xffffffffu, v, o);
        if (lane == 0) red[i * 8 + w] = v;
    }
    __syncthreads();
    if (threadIdx.x < 54) {
        float v = 0.f;
#pragma unroll
        for (int ww = 0; ww < 8; ww++) v += red[threadIdx.x * 8 + ww];
        g_part[blockIdx.x * 54 + threadIdx.x] = v;
    }

    // ---- last-block-done: reduce partials + fold BN into weights ----
    __shared__ bool is_last;
    __threadfence();
    if (threadIdx.x == 0) {
        int prev = atomicAdd(&g_ctr, 1);
        is_last = (prev == gridDim.x - 1);
    }
    __syncthreads();
    if (!is_last) return;

    __shared__ float st[64];
    {
        const int t = threadIdx.x;      // 256 threads
        const int g = t >> 2;           // stat index (0..63, 54 used)
        const int j = t & 3;
        float v = 0.f;
        if (g < 54)
            for (int b = j; b < STATS_BLOCKS; b += 4)
                v += g_part[b * 54 + g];
        v += __shfl_xor_sync(0xffffffffu, v, 1);
        v += __shfl_xor_sync(0xffffffffu, v, 2);
        if (j == 0 && g < 54) st[g] = v;
    }
    __syncthreads();

    if (threadIdx.x < COUT) {
        const int t = threadIdx.x;
        float wv[9];
#pragma unroll
        for (int k = 0; k < 9; k++) wv[k] = weight[k * COUT + t];
        const float invn = 1.f / (float)n;

        float mean = 0.f;
#pragma unroll
        for (int k = 0; k < 9; k++) mean += st[k] * wv[k];
        mean *= invn;

        float q = 0.f;
        int idx = 9;
#pragma unroll
        for (int jj = 0; jj < 9; jj++)
#pragma unroll
            for (int k = jj; k < 9; k++) {
                float term = st[idx++] * wv[jj] * wv[k];
                q += (jj == k) ? term : 2.f * term;
            }
        float var   = fmaxf(q * invn - mean * mean, 0.f);
        float scale = gamma[t] * rsqrtf(var + BN_EPS);
#pragma unroll
        for (int k = 0; k < 9; k++) g_wf[k * COUT + t] = wv[k] * scale;
        g_bf[t] = beta[t] - mean * scale;
    }
}

// ---------------------------------------------------------------------------
// K4: DENSE output pass, 256-pixel tiles (a tile = half a grid row).
//     Phase A: thread t stages the 9 taps of pixel (tile*256 + t) via
//              coalesced row loads into smem (3 float4, stride 48 B,
//              conflict-free), and ballot-compacts active pixels.
//     Phase B: half-warp per ACTIVE pixel; lane computes 4 channels;
//              3 broadcast LDS.128 + 36 FMA per point; coalesced 256 B row
//              streamed to out[idx].
// ---------------------------------------------------------------------------
__global__ __launch_bounds__(256) void k_output(float4* __restrict__ out) {
    __shared__ float4 sm[TILE * 3];
    __shared__ int   s_pix[TILE];     // compacted local pixel id
    __shared__ int   s_row[TILE];     // compacted output row
    __shared__ int   s_cnt;

    const int tid  = threadIdx.x;
    const int lane = tid & 31;
    const int wid  = tid >> 5;
    const int h    = lane >> 4;       // half-warp id (0/1)
    const int cl   = lane & 15;       // float4 channel group

    float4 w4[9];
#pragma unroll
    for (int k = 0; k < 9; k++)
        w4[k] = reinterpret_cast<const float4*>(g_wf)[k * 16 + cl];
    const float4 b4 = reinterpret_cast<const float4*>(g_bf)[cl];

    const int ntiles = NPIX / TILE;   // 8192
    for (int tile = blockIdx.x; tile < ntiles; tile += gridDim.x) {
        const int q0 = tile * TILE;
        const int y  = q0 >> 11;
        const int x0 = q0 & (WW - 1);

        if (tid == 0) s_cnt = 0;
        __syncthreads();

        // Phase A: coalesced tap staging + active compaction
        {
            const float* rb = g_grid + y * GW2 + x0 + tid;
            float s[9];
#pragma unroll
            for (int r = 0; r < 3; r++)
#pragma unroll
                for (int c = 0; c < 3; c++)
                    s[r * 3 + c] = rb[r * GW2 + c];
            sm[tid * 3 + 0] = make_float4(s[0], s[1], s[2], s[3]);
            sm[tid * 3 + 1] = make_float4(s[4], s[5], s[6], s[7]);
            sm[tid * 3 + 2] = make_float4(s[8], 0.f, 0.f, 0.f);

            const int oidx = g_idx[q0 + tid];
            const bool act = (oidx >= 0);
            const unsigned bal = __ballot_sync(0xffffffffu, act);
            int base;
            if (lane == 0) base = atomicAdd(&s_cnt, __popc(bal));
            base = __shfl_sync(0xffffffffu, base, 0);
            if (act) {
                const int pos = base + __popc(bal & ((1u << lane) - 1u));
                s_pix[pos] = tid;
                s_row[pos] = oidx;
            }
        }
        __syncthreads();

        // Phase B: half-warp per active pixel
        const int nact = s_cnt;
        for (int sl = wid * 2 + h; sl < nact; sl += 16) {
            const int j    = s_pix[sl];
            const int oidx = s_row[sl];
            const float4 A = sm[j * 3 + 0];
            const float4 B = sm[j * 3 + 1];
            const float s8 = sm[j * 3 + 2].x;

            float4 o = b4;
            o.x = fmaf(A.x, w4[0].x, o.x); o.y = fmaf(A.x, w4[0].y, o.y);
            o.z = fmaf(A.x, w4[0].z, o.z); o.w = fmaf(A.x, w4[0].w, o.w);
            o.x = fmaf(A.y, w4[1].x, o.x); o.y = fmaf(A.y, w4[1].y, o.y);
            o.z = fmaf(A.y, w4[1].z, o.z); o.w = fmaf(A.y, w4[1].w, o.w);
            o.x = fmaf(A.z, w4[2].x, o.x); o.y = fmaf(A.z, w4[2].y, o.y);
            o.z = fmaf(A.z, w4[2].z, o.z); o.w = fmaf(A.z, w4[2].w, o.w);
            o.x = fmaf(A.w, w4[3].x, o.x); o.y = fmaf(A.w, w4[3].y, o.y);
            o.z = fmaf(A.w, w4[3].z, o.z); o.w = fmaf(A.w, w4[3].w, o.w);
            o.x = fmaf(B.x, w4[4].x, o.x); o.y = fmaf(B.x, w4[4].y, o.y);
            o.z = fmaf(B.x, w4[4].z, o.z); o.w = fmaf(B.x, w4[4].w, o.w);
            o.x = fmaf(B.y, w4[5].x, o.x); o.y = fmaf(B.y, w4[5].y, o.y);
            o.z = fmaf(B.y, w4[5].z, o.z); o.w = fmaf(B.y, w4[5].w, o.w);
            o.x = fmaf(B.z, w4[6].x, o.x); o.y = fmaf(B.z, w4[6].y, o.y);
            o.z = fmaf(B.z, w4[6].z, o.z); o.w = fmaf(B.z, w4[6].w, o.w);
            o.x = fmaf(B.w, w4[7].x, o.x); o.y = fmaf(B.w, w4[7].y, o.y);
            o.z = fmaf(B.w, w4[7].z, o.z); o.w = fmaf(B.w, w4[7].w, o.w);
            o.x = fmaf(s8,  w4[8].x, o.x); o.y = fmaf(s8,  w4[8].y, o.y);
            o.z = fmaf(s8,  w4[8].z, o.z); o.w = fmaf(s8,  w4[8].w, o.w);

            o.x = fmaxf(o.x, 0.f); o.y = fmaxf(o.y, 0.f);
            o.z = fmaxf(o.z, 0.f); o.w = fmaxf(o.w, 0.f);
            __stcs(&out[(size_t)oidx * 16 + cl], o);
        }
        __syncthreads();
    }
}

// ---------------------------------------------------------------------------
// Launch: inputs are feats[N,1] f32, weight[9,1,64] f32, gamma[64], beta[64],
//         coords[N,2] i32. Output: [N,64] f32.
// ---------------------------------------------------------------------------
extern "C" void kernel_launch(void* const* d_in, const int* in_sizes, int n_in,
                              void* d_out, int out_size) {
    const float* feats  = (const float*)d_in[0];
    const float* weight = (const float*)d_in[1];
    const float* gamma  = (const float*)d_in[2];
    const float* beta   = (const float*)d_in[3];
    const int2*  coords = (const int2*)d_in[4];
    const int n = in_sizes[0];   // N (C_IN = 1)

    k_zero<<<1480, 256>>>();
    k_scatter<<<(n + 255) / 256, 256>>>(coords, feats, n);
    k_stats<<<STATS_BLOCKS, 256>>>(weight, gamma, beta, n);
    k_output<<<1480, 256>>>((float4*)d_out);
}